// round 15
// baseline (speedup 1.0000x reference)
#include <cuda_runtime.h>
#include <cuda_bf16.h>
#include <math.h>
#include <stdint.h>

// Problem constants
#define BATCH   4
#define NTOK    4096
#define DMODEL  1024
#define NHEAD   16
#define HDIM    64
#define KANCH   256
#define MROWS   (BATCH * NTOK)        // 16384
#define SCALE   0.125f

// ---------------------------------------------------------------------------
// Scratch (device globals). RULE: device symbols referenced ONLY from device
// code (host-shadow + GB300 ATS silently swallows host-passed symbol stores).
// ---------------------------------------------------------------------------
__device__ __align__(16) __nv_bfloat16 g_xhi[MROWS * DMODEL];
__device__ __align__(16) __nv_bfloat16 g_xlo[MROWS * DMODEL];
__device__ __align__(16) __nv_bfloat16 g_Qhi[MROWS * DMODEL];
__device__ __align__(16) __nv_bfloat16 g_Qlo[MROWS * DMODEL];
__device__ __align__(16) __nv_bfloat16 g_Khi[BATCH * KANCH * DMODEL];
__device__ __align__(16) __nv_bfloat16 g_Klo[BATCH * KANCH * DMODEL];
// V transposed per (b,h): [b][h][d][key]
__device__ __align__(16) __nv_bfloat16 g_Vthi[BATCH * NHEAD * HDIM * KANCH];
__device__ __align__(16) __nv_bfloat16 g_Vtlo[BATCH * NHEAD * HDIM * KANCH];
__device__ __align__(16) __nv_bfloat16 g_chi[MROWS * DMODEL];
__device__ __align__(16) __nv_bfloat16 g_clo[MROWS * DMODEL];
// Transposed+split weights: [N][K] K-major. 0=Wq 1=Wqt 2=Wk 3=Wv 4=Wo
__device__ __align__(16) __nv_bfloat16 g_Wh[5][DMODEL * DMODEL];
__device__ __align__(16) __nv_bfloat16 g_Wl[5][DMODEL * DMODEL];

// ---------------------------------------------------------------------------
// Primitives
// ---------------------------------------------------------------------------
__device__ __forceinline__ uint32_t smem_to_u32(const void* p) {
    uint32_t a;
    asm("{ .reg .u64 t; cvta.to.shared.u64 t, %1; cvt.u32.u64 %0, t; }" : "=r"(a) : "l"(p));
    return a;
}
#define CP16(d, s) \
    asm volatile("cp.async.cg.shared.global [%0], [%1], 16;" :: "r"(d), "l"(s))
#define CP_COMMIT() asm volatile("cp.async.commit_group;")

__device__ __forceinline__ void mma_bf16(float* c, const uint32_t* a,
                                         uint32_t b0, uint32_t b1) {
    asm volatile(
        "mma.sync.aligned.m16n8k16.row.col.f32.bf16.bf16.f32 "
        "{%0,%1,%2,%3}, {%4,%5,%6,%7}, {%8,%9}, {%0,%1,%2,%3};"
        : "+f"(c[0]), "+f"(c[1]), "+f"(c[2]), "+f"(c[3])
        : "r"(a[0]), "r"(a[1]), "r"(a[2]), "r"(a[3]), "r"(b0), "r"(b1));
}

__device__ __forceinline__ void split2(float v0, float v1, uint32_t& hi, uint32_t& lo) {
    __nv_bfloat16 h0 = __float2bfloat16(v0), h1 = __float2bfloat16(v1);
    __nv_bfloat162 hh; hh.x = h0; hh.y = h1;
    __nv_bfloat162 ll;
    ll.x = __float2bfloat16(v0 - __bfloat162float(h0));
    ll.y = __float2bfloat16(v1 - __bfloat162float(h1));
    hi = *reinterpret_cast<uint32_t*>(&hh);
    lo = *reinterpret_cast<uint32_t*>(&ll);
}

// 16B-chunk XOR swizzle on 64B rows (16 u32, chunks c∈0..3):
// stored chunk = c ^ ((row>>1)&3). -> u32 offset.
#define SW64(row, cc) ((((row) << 4)) + ((((cc) ^ (((row) >> 1) & 3))) << 2))

// ---------------------------------------------------------------------------
// bf16x3 GEMM mainloop: acc = A(128x1024) @ B^T(128x1024)
// 256 thr, 8 warps (4x2), warp tile 32x64, BK=32, 2-stage cp.async ring.
// smem: 64 KB dynamic (opt-in) -> 2 CTAs/SM.
// ---------------------------------------------------------------------------
#define GEMM_SMEM 65536

__device__ __forceinline__ void gemm_main(
    const __nv_bfloat16* __restrict__ Ahi, const __nv_bfloat16* __restrict__ Alo,
    const __nv_bfloat16* __restrict__ Bhi, const __nv_bfloat16* __restrict__ Blo,
    float acc[2][8][4])
{
    extern __shared__ uint32_t sm[];
    const int tid  = threadIdx.x;
    const int lane = tid & 31;
    const int wid  = tid >> 5;
    const int wm   = wid >> 1;
    const int wn   = wid & 1;
    const int g    = lane >> 2;
    const int t    = lane & 3;

#pragma unroll
    for (int i = 0; i < 2; i++)
#pragma unroll
        for (int j = 0; j < 8; j++)
#pragma unroll
            for (int k = 0; k < 4; k++) acc[i][j][k] = 0.f;

    const char* gp[4] = { (const char*)Ahi, (const char*)Alo,
                          (const char*)Bhi, (const char*)Blo };

    const int row = tid >> 1;
    const int c0  = (tid & 1) * 2;
    const uint32_t swo0 = SW64(row, c0);
    const uint32_t swo1 = SW64(row, c0 + 1);
    const uint32_t sb   = smem_to_u32(sm);
    const size_t   gof  = (size_t)row * 512 + c0 * 4;

#define G_ISSUE(c) do {                                                        \
        const uint32_t _st = ((uint32_t)((c) & 1)) * 8192u;                    \
        const size_t _gb = (gof + (size_t)(c) * 16) << 2;                      \
        _Pragma("unroll")                                                      \
        for (int m = 0; m < 4; m++) {                                          \
            CP16(sb + ((_st + m * 2048u + swo0) << 2), gp[m] + _gb);           \
            CP16(sb + ((_st + m * 2048u + swo1) << 2), gp[m] + _gb + 16);      \
        }                                                                      \
        CP_COMMIT();                                                           \
    } while (0)

    G_ISSUE(0);

    for (int c = 0; c < 32; c++) {
        asm volatile("cp.async.wait_group 0;");
        __syncthreads();
        if (c + 1 < 32) G_ISSUE(c + 1);

        const uint32_t* st = sm + (c & 1) * 8192;
#pragma unroll
        for (int ks = 0; ks < 2; ks++) {
            const int cA = ks * 2;
            uint32_t aHi[2][4], aLo[2][4];
#pragma unroll
            for (int mf = 0; mf < 2; mf++) {
                const int rA0 = wm * 32 + mf * 16 + g;
                const int rA1 = rA0 + 8;
                aHi[mf][0] = st[SW64(rA0, cA) + t];
                aHi[mf][1] = st[SW64(rA1, cA) + t];
                aHi[mf][2] = st[SW64(rA0, cA + 1) + t];
                aHi[mf][3] = st[SW64(rA1, cA + 1) + t];
                aLo[mf][0] = st[2048 + SW64(rA0, cA) + t];
                aLo[mf][1] = st[2048 + SW64(rA1, cA) + t];
                aLo[mf][2] = st[2048 + SW64(rA0, cA + 1) + t];
                aLo[mf][3] = st[2048 + SW64(rA1, cA + 1) + t];
            }
#pragma unroll
            for (int nq = 0; nq < 4; nq++) {
#pragma unroll
                for (int hf = 0; hf < 2; hf++) {
                    const int rB = wn * 64 + nq * 16 + hf * 8 + g;
                    const uint32_t b0h = st[4096 + SW64(rB, cA) + t];
                    const uint32_t b1h = st[4096 + SW64(rB, cA + 1) + t];
                    const uint32_t b0l = st[6144 + SW64(rB, cA) + t];
                    const uint32_t b1l = st[6144 + SW64(rB, cA + 1) + t];
                    float* cc0 = acc[0][nq * 2 + hf];
                    float* cc1 = acc[1][nq * 2 + hf];
                    mma_bf16(cc0, aHi[0], b0h, b1h);
                    mma_bf16(cc0, aHi[0], b0l, b1l);
                    mma_bf16(cc0, aLo[0], b0h, b1h);
                    mma_bf16(cc1, aHi[1], b0h, b1h);
                    mma_bf16(cc1, aHi[1], b0l, b1l);
                    mma_bf16(cc1, aLo[1], b0h, b1h);
                }
            }
        }
    }
#undef G_ISSUE
}

// ---------------------------------------------------------------------------
// Fused projection kernel: 1152 linear tiles (Q: [0,1024), K: [1024,1088),
// V transposed: [1088,1152)).
// ---------------------------------------------------------------------------
__global__ void __launch_bounds__(256, 2) proj_kernel(
    const float* __restrict__ bq, const float* __restrict__ bqt,
    const float* __restrict__ bk, const float* __restrict__ bv)
{
    const int idx  = blockIdx.x;
    const int lane = threadIdx.x & 31, wid = threadIdx.x >> 5;
    const int wm = wid >> 1, wn = wid & 1, g = lane >> 2, t = lane & 3;
    float acc[2][8][4];

    if (idx < 1024) {
        const int Mb = (idx >> 3) * 128;
        const int Nb = (idx & 7) * 128;
        const bool anchor = (Mb % NTOK) < KANCH;
        const int w = anchor ? 0 : 1;
        gemm_main(g_xhi + (size_t)Mb * DMODEL, g_xlo + (size_t)Mb * DMODEL,
                  g_Wh[w] + (size_t)Nb * DMODEL, g_Wl[w] + (size_t)Nb * DMODEL, acc);
        const float* bias = anchor ? bq : bqt;
        uint32_t* Hi = (uint32_t*)g_Qhi;
        uint32_t* Lo = (uint32_t*)g_Qlo;
#pragma unroll
        for (int mf = 0; mf < 2; mf++)
#pragma unroll
            for (int nf = 0; nf < 8; nf++) {
                const int row = Mb + wm * 32 + mf * 16 + g;
                const int col = Nb + wn * 64 + nf * 8 + t * 2;
                const float bx = bias[col], by = bias[col + 1];
                uint32_t h0, l0, h1, l1;
                split2(acc[mf][nf][0] + bx, acc[mf][nf][1] + by, h0, l0);
                split2(acc[mf][nf][2] + bx, acc[mf][nf][3] + by, h1, l1);
                Hi[(size_t)row * 512 + col / 2] = h0;
                Lo[(size_t)row * 512 + col / 2] = l0;
                Hi[(size_t)(row + 8) * 512 + col / 2] = h1;
                Lo[(size_t)(row + 8) * 512 + col / 2] = l1;
            }
    } else if (idx < 1088) {
        const int rem = idx - 1024;
        const int Mt = rem >> 3;
        const int Nb = (rem & 7) * 128;
        const int arow = (Mt >> 1) * NTOK + (Mt & 1) * 128;
        gemm_main(g_xhi + (size_t)arow * DMODEL, g_xlo + (size_t)arow * DMODEL,
                  g_Wh[2] + (size_t)Nb * DMODEL, g_Wl[2] + (size_t)Nb * DMODEL, acc);
        uint32_t* Hi = (uint32_t*)g_Khi;
        uint32_t* Lo = (uint32_t*)g_Klo;
#pragma unroll
        for (int mf = 0; mf < 2; mf++)
#pragma unroll
            for (int nf = 0; nf < 8; nf++) {
                const int row = Mt * 128 + wm * 32 + mf * 16 + g;
                const int col = Nb + wn * 64 + nf * 8 + t * 2;
                const float bx = bk[col], by = bk[col + 1];
                uint32_t h0, l0, h1, l1;
                split2(acc[mf][nf][0] + bx, acc[mf][nf][1] + by, h0, l0);
                split2(acc[mf][nf][2] + bx, acc[mf][nf][3] + by, h1, l1);
                Hi[(size_t)row * 512 + col / 2] = h0;
                Lo[(size_t)row * 512 + col / 2] = l0;
                Hi[(size_t)(row + 8) * 512 + col / 2] = h1;
                Lo[(size_t)(row + 8) * 512 + col / 2] = l1;
            }
    } else {
        const int rem = idx - 1088;
        const int Mt = rem >> 3;
        const int Nb = (rem & 7) * 128;
        const int arow = (Mt >> 1) * NTOK + (Mt & 1) * 128;
        gemm_main(g_xhi + (size_t)arow * DMODEL, g_xlo + (size_t)arow * DMODEL,
                  g_Wh[3] + (size_t)Nb * DMODEL, g_Wl[3] + (size_t)Nb * DMODEL, acc);
#pragma unroll
        for (int mf = 0; mf < 2; mf++)
#pragma unroll
            for (int nf = 0; nf < 8; nf++) {
                const int col = Nb + wn * 64 + nf * 8 + t * 2;
                const int h = col >> 6, d = col & 63;
#pragma unroll
                for (int rr = 0; rr < 2; rr++) {
                    const int a = Mt * 128 + wm * 32 + mf * 16 + g + rr * 8;
                    const int b = a >> 8, tok = a & 255;
                    const float v0 = acc[mf][nf][rr * 2 + 0] + bv[col];
                    const float v1 = acc[mf][nf][rr * 2 + 1] + bv[col + 1];
                    const size_t i0 = ((size_t)((b * NHEAD + h) * HDIM + d)) * KANCH + tok;
                    __nv_bfloat16 h0 = __float2bfloat16(v0);
                    __nv_bfloat16 h1 = __float2bfloat16(v1);
                    g_Vthi[i0] = h0;
                    g_Vtlo[i0] = __float2bfloat16(v0 - __bfloat162float(h0));
                    g_Vthi[i0 + KANCH] = h1;
                    g_Vtlo[i0 + KANCH] = __float2bfloat16(v1 - __bfloat162float(h1));
                }
            }
    }
}

// ---- Output projection: ctx(hi/lo) @ Wo + bo -> fp32 out ----
__global__ void __launch_bounds__(256, 2) oproj_kernel(
    const float* __restrict__ bo, float* __restrict__ out)
{
    const int Mb = blockIdx.y * 128;
    const int Nb = blockIdx.x * 128;
    float acc[2][8][4];
    gemm_main(g_chi + (size_t)Mb * DMODEL, g_clo + (size_t)Mb * DMODEL,
              g_Wh[4] + (size_t)Nb * DMODEL, g_Wl[4] + (size_t)Nb * DMODEL, acc);
    const int lane = threadIdx.x & 31, wid = threadIdx.x >> 5;
    const int wm = wid >> 1, wn = wid & 1, g = lane >> 2, t = lane & 3;
#pragma unroll
    for (int mf = 0; mf < 2; mf++)
#pragma unroll
        for (int nf = 0; nf < 8; nf++) {
            const int row = Mb + wm * 32 + mf * 16 + g;
            const int col = Nb + wn * 64 + nf * 8 + t * 2;
            const float bx = bo[col], by = bo[col + 1];
            float2 v0 = { acc[mf][nf][0] + bx, acc[mf][nf][1] + by };
            float2 v1 = { acc[mf][nf][2] + bx, acc[mf][nf][3] + by };
            *reinterpret_cast<float2*>(out + (size_t)row * DMODEL + col) = v0;
            *reinterpret_cast<float2*>(out + (size_t)(row + 8) * DMODEL + col) = v1;
        }
}

// ---------------------------------------------------------------------------
// Fused prep: blocks [0,4096) split x; blocks [4096,9216) weight transpose.
// ---------------------------------------------------------------------------
__global__ void __launch_bounds__(256) prep_kernel(
    const float* __restrict__ x,
    const float* __restrict__ Wq, const float* __restrict__ Wqt,
    const float* __restrict__ Wk, const float* __restrict__ Wv,
    const float* __restrict__ Wo)
{
    __shared__ float tbuf[32][33];
    const int tid = threadIdx.x;

    if (blockIdx.x < 4096) {
        const int n4 = MROWS * DMODEL / 4;
        for (int i = blockIdx.x * 256 + tid; i < n4; i += 4096 * 256) {
            float4 v = reinterpret_cast<const float4*>(x)[i];
            uint32_t hA, lA, hB, lB;
            split2(v.x, v.y, hA, lA);
            split2(v.z, v.w, hB, lB);
            reinterpret_cast<uint32_t*>(g_xhi)[i * 2 + 0] = hA;
            reinterpret_cast<uint32_t*>(g_xhi)[i * 2 + 1] = hB;
            reinterpret_cast<uint32_t*>(g_xlo)[i * 2 + 0] = lA;
            reinterpret_cast<uint32_t*>(g_xlo)[i * 2 + 1] = lB;
        }
        return;
    }

    const int widx = blockIdx.x - 4096;
    const int z   = widx >> 10;
    const int rem = widx & 1023;
    const int bx  = rem & 31;
    const int by  = rem >> 5;
    const int tx  = tid & 31;
    const int ty  = tid >> 5;

    const float* src;
    switch (z) {
        case 0: src = Wq;  break;
        case 1: src = Wqt; break;
        case 2: src = Wk;  break;
        case 3: src = Wv;  break;
        default: src = Wo; break;
    }
    __nv_bfloat16* dh = g_Wh[z];
    __nv_bfloat16* dl = g_Wl[z];
    const int n0 = bx * 32, k0 = by * 32;
    for (int i = ty; i < 32; i += 8)
        tbuf[i][tx] = src[(size_t)(k0 + i) * DMODEL + n0 + tx];
    __syncthreads();
    for (int i = ty; i < 32; i += 8) {
        float v = tbuf[tx][i];
        __nv_bfloat16 h = __float2bfloat16(v);
        size_t idx = (size_t)(n0 + i) * DMODEL + k0 + tx;
        dh[idx] = h;
        dl[idx] = __float2bfloat16(v - __bfloat162float(h));
    }
}

// ---------------------------------------------------------------------------
// Flash tensor-core attention, fixed-shift softmax, 2-stage cp.async K/V.
// CTA = 64 Q rows x one (b,h), 128 threads (4 warps x 16 rows).
// Q fragments loaded DIRECTLY from gmem (no Q smem stage).
// Dynamic smem = 2 stages x 4864 u32 = 38912 B -> 4 CTAs/SM (regs 128).
// Stage s at s*4864: ksh +0 (1152), ksl +1152, vsh +2304 (1280), vsl +3584.
// ---------------------------------------------------------------------------
#define ATTN_SMEM 38912

__global__ void __launch_bounds__(128, 4) attn_mma_kernel()
{
    extern __shared__ uint32_t sma[];
    const uint32_t sb = smem_to_u32(sma);

    const int b = blockIdx.z, h = blockIdx.y;
    const int n0 = blockIdx.x * 64;
    const int tid = threadIdx.x, lane = tid & 31, wid = tid >> 5;
    const int g = lane >> 2, t = lane & 3;
    const int wr = wid * 16;

    const char* kH = (const char*)g_Khi;
    const char* kL = (const char*)g_Klo;
    const char* vH = (const char*)g_Vthi;
    const char* vL = (const char*)g_Vtlo;

#define A_ISSUE(ch) do {                                                         \
        const uint32_t _sbase = ((uint32_t)((ch) & 1)) * 4864u;                  \
        _Pragma("unroll")                                                        \
        for (int k = 0; k < 8; k++) {                                            \
            const int i = tid + k * 128;                                         \
            if (i < 512) {                                                       \
                const int mat = i >> 8, rr = (i & 255) >> 3, q4 = i & 7;         \
                const size_t gb = (((size_t)(b * KANCH + (ch) * 32 + rr) * 128   \
                                    + h * 8 + q4)) << 4;                         \
                const uint32_t dof = _sbase + (mat ? 1152u : 0u) + rr * 36 + q4 * 4; \
                CP16(sb + (dof << 2), (mat ? kL : kH) + gb);                     \
            } else {                                                             \
                const int j = i - 512;                                           \
                const int mat = j >> 8, dd = (j & 255) >> 2, q4 = j & 3;         \
                const size_t gb = (((size_t)((b * NHEAD + h) * HDIM + dd) * 32   \
                                    + (ch) * 4 + q4)) << 4;                      \
                const uint32_t dof = _sbase + 2304u + (mat ? 1280u : 0u) + dd * 20 + q4 * 4; \
                CP16(sb + (dof << 2), (mat ? vL : vH) + gb);                     \
            }                                                                    \
        }                                                                        \
        CP_COMMIT();                                                             \
    } while (0)

    A_ISSUE(0);

    // ---- Q fragments directly from gmem (coalesced 16B per quad) ----
    uint32_t qh[4][4], ql[4][4];
    {
        const uint32_t* QHi = (const uint32_t*)g_Qhi;
        const uint32_t* QLo = (const uint32_t*)g_Qlo;
        const size_t r0 = (size_t)(b * NTOK + n0 + wr + g) * 512 + h * 32;
        const size_t r1 = r0 + 8 * 512;
#pragma unroll
        for (int ks = 0; ks < 4; ks++) {
            const int cOff = ks * 8 + t;
            qh[ks][0] = QHi[r0 + cOff];
            qh[ks][1] = QHi[r1 + cOff];
            qh[ks][2] = QHi[r0 + cOff + 4];
            qh[ks][3] = QHi[r1 + cOff + 4];
            ql[ks][0] = QLo[r0 + cOff];
            ql[ks][1] = QLo[r1 + cOff];
            ql[ks][2] = QLo[r0 + cOff + 4];
            ql[ks][3] = QLo[r1 + cOff + 4];
        }
    }

    asm volatile("cp.async.wait_group 0;");
    __syncthreads();

    float o[8][4];
#pragma unroll
    for (int i = 0; i < 8; i++)
#pragma unroll
        for (int j = 0; j < 4; j++) o[i][j] = 0.f;
    float lA = 0.f, lB = 0.f;

    for (int ch = 0; ch < 8; ch++) {
        if (ch + 1 < 8) A_ISSUE(ch + 1);

        const uint32_t* st = sma + (ch & 1) * 4864;
        const uint32_t* ksh = st;
        const uint32_t* ksl = st + 1152;
        const uint32_t* vsh = st + 2304;
        const uint32_t* vsl = st + 3584;

        // ---- Scores for this 32-key chunk ----
        float s[4][4];
#pragma unroll
        for (int i = 0; i < 4; i++)
#pragma unroll
            for (int j = 0; j < 4; j++) s[i][j] = 0.f;
#pragma unroll
        for (int nfl = 0; nfl < 4; nfl++) {
#pragma unroll
            for (int ks = 0; ks < 4; ks++) {
                const int rb = (nfl * 8 + g) * 36 + ks * 8 + t;
                const uint32_t b0h = ksh[rb], b1h = ksh[rb + 4];
                const uint32_t b0l = ksl[rb], b1l = ksl[rb + 4];
                mma_bf16(s[nfl], qh[ks], b0h, b1h);
                mma_bf16(s[nfl], qh[ks], b0l, b1l);
                mma_bf16(s[nfl], ql[ks], b0h, b1h);
            }
        }

        // ---- Fixed-shift softmax: p = exp(s*SCALE) directly ----
#pragma unroll
        for (int nf = 0; nf < 4; nf++) {
            s[nf][0] = __expf(s[nf][0] * SCALE); lA += s[nf][0];
            s[nf][1] = __expf(s[nf][1] * SCALE); lA += s[nf][1];
            s[nf][2] = __expf(s[nf][2] * SCALE); lB += s[nf][2];
            s[nf][3] = __expf(s[nf][3] * SCALE); lB += s[nf][3];
        }

        // ---- P·V for this chunk ----
#pragma unroll
        for (int kk = 0; kk < 2; kk++) {
            const int j0 = kk * 2;
            uint32_t ah[4], al[4];
            split2(s[j0][0],     s[j0][1],     ah[0], al[0]);
            split2(s[j0][2],     s[j0][3],     ah[1], al[1]);
            split2(s[j0 + 1][0], s[j0 + 1][1], ah[2], al[2]);
            split2(s[j0 + 1][2], s[j0 + 1][3], ah[3], al[3]);
#pragma unroll
            for (int nf = 0; nf < 8; nf++) {
                const int rb = (nf * 8 + g) * 20 + kk * 8 + t;
                const uint32_t b0h = vsh[rb], b1h = vsh[rb + 4];
                const uint32_t b0l = vsl[rb], b1l = vsl[rb + 4];
                mma_bf16(o[nf], ah, b0h, b1h);
                mma_bf16(o[nf], ah, b0l, b1l);
                mma_bf16(o[nf], al, b0h, b1h);
            }
        }

        if (ch + 1 < 8) {
            asm volatile("cp.async.wait_group 0;");
            __syncthreads();
        }
    }
#undef A_ISSUE

    // ---- Final l reduction across the quad, normalize, store ctx ----
    lA += __shfl_xor_sync(0xffffffffu, lA, 1);
    lA += __shfl_xor_sync(0xffffffffu, lA, 2);
    lB += __shfl_xor_sync(0xffffffffu, lB, 1);
    lB += __shfl_xor_sync(0xffffffffu, lB, 2);
    const float invA = 1.f / lA, invB = 1.f / lB;

    const size_t rowA = (size_t)(b * NTOK + n0 + wr + g);
    const size_t rowB = rowA + 8;
    uint32_t* Hi = (uint32_t*)g_chi;
    uint32_t* Lo = (uint32_t*)g_clo;
#pragma unroll
    for (int nf = 0; nf < 8; nf++) {
        const int col = h * 64 + nf * 8 + t * 2;
        uint32_t h0, l0, h1, l1;
        split2(o[nf][0] * invA, o[nf][1] * invA, h0, l0);
        split2(o[nf][2] * invB, o[nf][3] * invB, h1, l1);
        Hi[rowA * 512 + col / 2] = h0;
        Lo[rowA * 512 + col / 2] = l0;
        Hi[rowB * 512 + col / 2] = h1;
        Lo[rowB * 512 + col / 2] = l1;
    }
}

// ---------------------------------------------------------------------------
// kernel_launch
// ---------------------------------------------------------------------------
extern "C" void kernel_launch(void* const* d_in, const int* in_sizes, int n_in,
                              void* d_out, int out_size)
{
    const float* x   = (const float*)d_in[0];
    const float* Wq  = (const float*)d_in[1];
    const float* bq  = (const float*)d_in[2];
    const float* Wk  = (const float*)d_in[3];
    const float* bk  = (const float*)d_in[4];
    const float* Wv  = (const float*)d_in[5];
    const float* bv  = (const float*)d_in[6];
    const float* Wqt = (const float*)d_in[7];
    const float* bqt = (const float*)d_in[8];
    const float* Wo  = (const float*)d_in[9];
    const float* bo  = (const float*)d_in[10];
    float* out = (float*)d_out;

    static bool attr_done = false;
    if (!attr_done) {
        cudaFuncSetAttribute(proj_kernel,  cudaFuncAttributeMaxDynamicSharedMemorySize, GEMM_SMEM);
        cudaFuncSetAttribute(oproj_kernel, cudaFuncAttributeMaxDynamicSharedMemorySize, GEMM_SMEM);
        attr_done = true;
    }

    // Fused prep: x split (4096 blocks) + weight transpose/split (5120 blocks)
    prep_kernel<<<9216, 256>>>(x, Wq, Wqt, Wk, Wv, Wo);

    proj_kernel<<<1152, 256, GEMM_SMEM>>>(bq, bqt, bk, bv);

    attn_mma_kernel<<<dim3(NTOK / 64, NHEAD, BATCH), 128, ATTN_SMEM>>>();

    oproj_kernel<<<dim3(8, 128), 256, GEMM_SMEM>>>(bo, out);
}

// round 16
// speedup vs baseline: 1.2877x; 1.2877x over previous
#include <cuda_runtime.h>
#include <cuda_fp16.h>
#include <math.h>
#include <stdint.h>

// Problem constants
#define BATCH   4
#define NTOK    4096
#define DMODEL  1024
#define NHEAD   16
#define HDIM    64
#define KANCH   256
#define MROWS   (BATCH * NTOK)        // 16384
#define SCALE   0.125f

// ---------------------------------------------------------------------------
// Scratch (device globals). RULE: device symbols referenced ONLY from device
// code (host-shadow + GB300 ATS silently swallows host-passed symbol stores).
// All activation tensors stored as fp16 hi/lo (exact to ~2^-22); weights
// rounded ONCE to fp16 (error ~2.3e-4 rel, the accuracy budget).
// ---------------------------------------------------------------------------
__device__ __align__(16) __half g_xhi[MROWS * DMODEL];
__device__ __align__(16) __half g_xlo[MROWS * DMODEL];
__device__ __align__(16) __half g_Qhi[MROWS * DMODEL];
__device__ __align__(16) __half g_Qlo[MROWS * DMODEL];
__device__ __align__(16) __half g_Khi[BATCH * KANCH * DMODEL];
__device__ __align__(16) __half g_Klo[BATCH * KANCH * DMODEL];
// V transposed per (b,h): [b][h][d][key]
__device__ __align__(16) __half g_Vthi[BATCH * NHEAD * HDIM * KANCH];
__device__ __align__(16) __half g_Vtlo[BATCH * NHEAD * HDIM * KANCH];
__device__ __align__(16) __half g_chi[MROWS * DMODEL];
__device__ __align__(16) __half g_clo[MROWS * DMODEL];
// Transposed weights [N][K] K-major, single fp16. 0=Wq 1=Wqt 2=Wk 3=Wv 4=Wo
__device__ __align__(16) __half g_W[5][DMODEL * DMODEL];

// ---------------------------------------------------------------------------
// Primitives
// ---------------------------------------------------------------------------
__device__ __forceinline__ uint32_t smem_to_u32(const void* p) {
    uint32_t a;
    asm("{ .reg .u64 t; cvta.to.shared.u64 t, %1; cvt.u32.u64 %0, t; }" : "=r"(a) : "l"(p));
    return a;
}
#define CP16(d, s) \
    asm volatile("cp.async.cg.shared.global [%0], [%1], 16;" :: "r"(d), "l"(s))
#define CP_COMMIT() asm volatile("cp.async.commit_group;")

__device__ __forceinline__ void mma_f16(float* c, const uint32_t* a,
                                        uint32_t b0, uint32_t b1) {
    asm volatile(
        "mma.sync.aligned.m16n8k16.row.col.f32.f16.f16.f32 "
        "{%0,%1,%2,%3}, {%4,%5,%6,%7}, {%8,%9}, {%0,%1,%2,%3};"
        : "+f"(c[0]), "+f"(c[1]), "+f"(c[2]), "+f"(c[3])
        : "r"(a[0]), "r"(a[1]), "r"(a[2]), "r"(a[3]), "r"(b0), "r"(b1));
}

__device__ __forceinline__ void split2h(float v0, float v1, uint32_t& hi, uint32_t& lo) {
    __half h0 = __float2half_rn(v0), h1 = __float2half_rn(v1);
    __half2 hh = __halves2half2(h0, h1);
    __half2 ll = __halves2half2(__float2half_rn(v0 - __half2float(h0)),
                                __float2half_rn(v1 - __half2float(h1)));
    hi = *reinterpret_cast<uint32_t*>(&hh);
    lo = *reinterpret_cast<uint32_t*>(&ll);
}

// 16B-chunk XOR swizzle on 64B rows (16 u32, chunks c∈0..3):
// stored chunk = c ^ ((row>>1)&3). -> u32 offset.
#define SW64(row, cc) ((((row) << 4)) + ((((cc) ^ (((row) >> 1) & 3))) << 2))

// ---------------------------------------------------------------------------
// fp16 2-product GEMM mainloop: acc = (Ah+Al)(128x1024) @ Wh^T(128x1024)
// 256 thr, 8 warps (4x2), warp tile 32x64, BK=32, 2-stage cp.async ring.
// 3 operand mats per stage (Ahi|Alo|W, 8KB each) -> 48KB dynamic, 2 CTAs/SM.
// Per (k16,nq,hf): 2 MMAs per mf (Ah*W, Al*W) -> 64 MMAs/warp/chunk (was 96).
// ---------------------------------------------------------------------------
#define GEMM_SMEM 49152

__device__ __forceinline__ void gemm_main(
    const __half* __restrict__ Ahi, const __half* __restrict__ Alo,
    const __half* __restrict__ W,
    float acc[2][8][4])
{
    extern __shared__ uint32_t sm[];
    const int tid  = threadIdx.x;
    const int lane = tid & 31;
    const int wid  = tid >> 5;
    const int wm   = wid >> 1;
    const int wn   = wid & 1;
    const int g    = lane >> 2;
    const int t    = lane & 3;

#pragma unroll
    for (int i = 0; i < 2; i++)
#pragma unroll
        for (int j = 0; j < 8; j++)
#pragma unroll
            for (int k = 0; k < 4; k++) acc[i][j][k] = 0.f;

    const char* gp[3] = { (const char*)Ahi, (const char*)Alo, (const char*)W };

    const int row = tid >> 1;
    const int c0  = (tid & 1) * 2;
    const uint32_t swo0 = SW64(row, c0);
    const uint32_t swo1 = SW64(row, c0 + 1);
    const uint32_t sb   = smem_to_u32(sm);
    const size_t   gof  = (size_t)row * 512 + c0 * 4;

#define G_ISSUE(c) do {                                                        \
        const uint32_t _st = ((uint32_t)((c) & 1)) * 6144u;                    \
        const size_t _gb = (gof + (size_t)(c) * 16) << 2;                      \
        _Pragma("unroll")                                                      \
        for (int m = 0; m < 3; m++) {                                          \
            CP16(sb + ((_st + m * 2048u + swo0) << 2), gp[m] + _gb);           \
            CP16(sb + ((_st + m * 2048u + swo1) << 2), gp[m] + _gb + 16);      \
        }                                                                      \
        CP_COMMIT();                                                           \
    } while (0)

    G_ISSUE(0);

    for (int c = 0; c < 32; c++) {
        asm volatile("cp.async.wait_group 0;");
        __syncthreads();
        if (c + 1 < 32) G_ISSUE(c + 1);

        const uint32_t* st = sm + (c & 1) * 6144;
#pragma unroll
        for (int ks = 0; ks < 2; ks++) {
            const int cA = ks * 2;
            uint32_t aHi[2][4], aLo[2][4];
#pragma unroll
            for (int mf = 0; mf < 2; mf++) {
                const int rA0 = wm * 32 + mf * 16 + g;
                const int rA1 = rA0 + 8;
                aHi[mf][0] = st[SW64(rA0, cA) + t];
                aHi[mf][1] = st[SW64(rA1, cA) + t];
                aHi[mf][2] = st[SW64(rA0, cA + 1) + t];
                aHi[mf][3] = st[SW64(rA1, cA + 1) + t];
                aLo[mf][0] = st[2048 + SW64(rA0, cA) + t];
                aLo[mf][1] = st[2048 + SW64(rA1, cA) + t];
                aLo[mf][2] = st[2048 + SW64(rA0, cA + 1) + t];
                aLo[mf][3] = st[2048 + SW64(rA1, cA + 1) + t];
            }
#pragma unroll
            for (int nq = 0; nq < 4; nq++) {
#pragma unroll
                for (int hf = 0; hf < 2; hf++) {
                    const int rB = wn * 64 + nq * 16 + hf * 8 + g;
                    const uint32_t b0 = st[4096 + SW64(rB, cA) + t];
                    const uint32_t b1 = st[4096 + SW64(rB, cA + 1) + t];
                    float* cc0 = acc[0][nq * 2 + hf];
                    float* cc1 = acc[1][nq * 2 + hf];
                    mma_f16(cc0, aHi[0], b0, b1);
                    mma_f16(cc0, aLo[0], b0, b1);
                    mma_f16(cc1, aHi[1], b0, b1);
                    mma_f16(cc1, aLo[1], b0, b1);
                }
            }
        }
    }
#undef G_ISSUE
}

// ---------------------------------------------------------------------------
// Fused projection kernel: 1152 linear tiles (Q: [0,1024), K: [1024,1088),
// V transposed: [1088,1152)).
// ---------------------------------------------------------------------------
__global__ void __launch_bounds__(256, 2) proj_kernel(
    const float* __restrict__ bq, const float* __restrict__ bqt,
    const float* __restrict__ bk, const float* __restrict__ bv)
{
    const int idx  = blockIdx.x;
    const int lane = threadIdx.x & 31, wid = threadIdx.x >> 5;
    const int wm = wid >> 1, wn = wid & 1, g = lane >> 2, t = lane & 3;
    float acc[2][8][4];

    if (idx < 1024) {
        const int Mb = (idx >> 3) * 128;
        const int Nb = (idx & 7) * 128;
        const bool anchor = (Mb % NTOK) < KANCH;
        const int w = anchor ? 0 : 1;
        gemm_main(g_xhi + (size_t)Mb * DMODEL, g_xlo + (size_t)Mb * DMODEL,
                  g_W[w] + (size_t)Nb * DMODEL, acc);
        const float* bias = anchor ? bq : bqt;
        uint32_t* Hi = (uint32_t*)g_Qhi;
        uint32_t* Lo = (uint32_t*)g_Qlo;
#pragma unroll
        for (int mf = 0; mf < 2; mf++)
#pragma unroll
            for (int nf = 0; nf < 8; nf++) {
                const int row = Mb + wm * 32 + mf * 16 + g;
                const int col = Nb + wn * 64 + nf * 8 + t * 2;
                const float bx = bias[col], by = bias[col + 1];
                uint32_t h0, l0, h1, l1;
                split2h(acc[mf][nf][0] + bx, acc[mf][nf][1] + by, h0, l0);
                split2h(acc[mf][nf][2] + bx, acc[mf][nf][3] + by, h1, l1);
                Hi[(size_t)row * 512 + col / 2] = h0;
                Lo[(size_t)row * 512 + col / 2] = l0;
                Hi[(size_t)(row + 8) * 512 + col / 2] = h1;
                Lo[(size_t)(row + 8) * 512 + col / 2] = l1;
            }
    } else if (idx < 1088) {
        const int rem = idx - 1024;
        const int Mt = rem >> 3;
        const int Nb = (rem & 7) * 128;
        const int arow = (Mt >> 1) * NTOK + (Mt & 1) * 128;
        gemm_main(g_xhi + (size_t)arow * DMODEL, g_xlo + (size_t)arow * DMODEL,
                  g_W[2] + (size_t)Nb * DMODEL, acc);
        uint32_t* Hi = (uint32_t*)g_Khi;
        uint32_t* Lo = (uint32_t*)g_Klo;
#pragma unroll
        for (int mf = 0; mf < 2; mf++)
#pragma unroll
            for (int nf = 0; nf < 8; nf++) {
                const int row = Mt * 128 + wm * 32 + mf * 16 + g;
                const int col = Nb + wn * 64 + nf * 8 + t * 2;
                const float bx = bk[col], by = bk[col + 1];
                uint32_t h0, l0, h1, l1;
                split2h(acc[mf][nf][0] + bx, acc[mf][nf][1] + by, h0, l0);
                split2h(acc[mf][nf][2] + bx, acc[mf][nf][3] + by, h1, l1);
                Hi[(size_t)row * 512 + col / 2] = h0;
                Lo[(size_t)row * 512 + col / 2] = l0;
                Hi[(size_t)(row + 8) * 512 + col / 2] = h1;
                Lo[(size_t)(row + 8) * 512 + col / 2] = l1;
            }
    } else {
        const int rem = idx - 1088;
        const int Mt = rem >> 3;
        const int Nb = (rem & 7) * 128;
        const int arow = (Mt >> 1) * NTOK + (Mt & 1) * 128;
        gemm_main(g_xhi + (size_t)arow * DMODEL, g_xlo + (size_t)arow * DMODEL,
                  g_W[3] + (size_t)Nb * DMODEL, acc);
#pragma unroll
        for (int mf = 0; mf < 2; mf++)
#pragma unroll
            for (int nf = 0; nf < 8; nf++) {
                const int col = Nb + wn * 64 + nf * 8 + t * 2;
                const int h = col >> 6, d = col & 63;
#pragma unroll
                for (int rr = 0; rr < 2; rr++) {
                    const int a = Mt * 128 + wm * 32 + mf * 16 + g + rr * 8;
                    const int b = a >> 8, tok = a & 255;
                    const float v0 = acc[mf][nf][rr * 2 + 0] + bv[col];
                    const float v1 = acc[mf][nf][rr * 2 + 1] + bv[col + 1];
                    const size_t i0 = ((size_t)((b * NHEAD + h) * HDIM + d)) * KANCH + tok;
                    __half h0 = __float2half_rn(v0);
                    __half h1 = __float2half_rn(v1);
                    g_Vthi[i0] = h0;
                    g_Vtlo[i0] = __float2half_rn(v0 - __half2float(h0));
                    g_Vthi[i0 + KANCH] = h1;
                    g_Vtlo[i0 + KANCH] = __float2half_rn(v1 - __half2float(h1));
                }
            }
    }
}

// ---- Output projection: ctx(hi/lo) @ Wo + bo -> fp32 out ----
__global__ void __launch_bounds__(256, 2) oproj_kernel(
    const float* __restrict__ bo, float* __restrict__ out)
{
    const int Mb = blockIdx.y * 128;
    const int Nb = blockIdx.x * 128;
    float acc[2][8][4];
    gemm_main(g_chi + (size_t)Mb * DMODEL, g_clo + (size_t)Mb * DMODEL,
              g_W[4] + (size_t)Nb * DMODEL, acc);
    const int lane = threadIdx.x & 31, wid = threadIdx.x >> 5;
    const int wm = wid >> 1, wn = wid & 1, g = lane >> 2, t = lane & 3;
#pragma unroll
    for (int mf = 0; mf < 2; mf++)
#pragma unroll
        for (int nf = 0; nf < 8; nf++) {
            const int row = Mb + wm * 32 + mf * 16 + g;
            const int col = Nb + wn * 64 + nf * 8 + t * 2;
            const float bx = bo[col], by = bo[col + 1];
            float2 v0 = { acc[mf][nf][0] + bx, acc[mf][nf][1] + by };
            float2 v1 = { acc[mf][nf][2] + bx, acc[mf][nf][3] + by };
            *reinterpret_cast<float2*>(out + (size_t)row * DMODEL + col) = v0;
            *reinterpret_cast<float2*>(out + (size_t)(row + 8) * DMODEL + col) = v1;
        }
}

// ---------------------------------------------------------------------------
// Fused prep: blocks [0,4096) split x (fp16 hi/lo); blocks [4096,9216)
// transpose the 5 weight matrices, rounding ONCE to fp16.
// ---------------------------------------------------------------------------
__global__ void __launch_bounds__(256) prep_kernel(
    const float* __restrict__ x,
    const float* __restrict__ Wq, const float* __restrict__ Wqt,
    const float* __restrict__ Wk, const float* __restrict__ Wv,
    const float* __restrict__ Wo)
{
    __shared__ float tbuf[32][33];
    const int tid = threadIdx.x;

    if (blockIdx.x < 4096) {
        const int n4 = MROWS * DMODEL / 4;
        for (int i = blockIdx.x * 256 + tid; i < n4; i += 4096 * 256) {
            float4 v = reinterpret_cast<const float4*>(x)[i];
            uint32_t hA, lA, hB, lB;
            split2h(v.x, v.y, hA, lA);
            split2h(v.z, v.w, hB, lB);
            reinterpret_cast<uint32_t*>(g_xhi)[i * 2 + 0] = hA;
            reinterpret_cast<uint32_t*>(g_xhi)[i * 2 + 1] = hB;
            reinterpret_cast<uint32_t*>(g_xlo)[i * 2 + 0] = lA;
            reinterpret_cast<uint32_t*>(g_xlo)[i * 2 + 1] = lB;
        }
        return;
    }

    const int widx = blockIdx.x - 4096;
    const int z   = widx >> 10;
    const int rem = widx & 1023;
    const int bx  = rem & 31;
    const int by  = rem >> 5;
    const int tx  = tid & 31;
    const int ty  = tid >> 5;

    const float* src;
    switch (z) {
        case 0: src = Wq;  break;
        case 1: src = Wqt; break;
        case 2: src = Wk;  break;
        case 3: src = Wv;  break;
        default: src = Wo; break;
    }
    __half* dh = g_W[z];
    const int n0 = bx * 32, k0 = by * 32;
    for (int i = ty; i < 32; i += 8)
        tbuf[i][tx] = src[(size_t)(k0 + i) * DMODEL + n0 + tx];
    __syncthreads();
    for (int i = ty; i < 32; i += 8)
        dh[(size_t)(n0 + i) * DMODEL + k0 + tx] = __float2half_rn(tbuf[tx][i]);
}

// ---------------------------------------------------------------------------
// Flash tensor-core attention (round-14 structure), fp16 3-product,
// fixed-shift softmax, 2-stage cp.async K/V pipeline.
// CTA = 128 Q rows x one (b,h), 256 thr. Dynamic smem 75776 B; 2 CTAs/SM.
// ---------------------------------------------------------------------------
#define ATTN_SMEM 75776

__global__ void __launch_bounds__(256, 2) attn_mma_kernel()
{
    extern __shared__ uint32_t sma[];
    const uint32_t sb = smem_to_u32(sma);

    const int b = blockIdx.z, h = blockIdx.y;
    const int n0 = blockIdx.x * 128;
    const int tid = threadIdx.x, lane = tid & 31, wid = tid >> 5;
    const int g = lane >> 2, t = lane & 3;
    const int wr = wid * 16;

    const char* qH = (const char*)g_Qhi;
    const char* qL = (const char*)g_Qlo;
    const char* kH = (const char*)g_Khi;
    const char* kL = (const char*)g_Klo;
    const char* vH = (const char*)g_Vthi;
    const char* vL = (const char*)g_Vtlo;

    // ---- Q tile via cp.async: 2048 x 16B ----
#pragma unroll
    for (int k = 0; k < 8; k++) {
        const int i = tid + k * 256;
        const int mat = i >> 10, rr = (i & 1023) >> 3, q4 = i & 7;
        const size_t gb = (((size_t)(b * NTOK + n0 + rr) * 128 + h * 8 + q4)) << 4;
        const uint32_t dof = (uint32_t)(mat ? 4608 : 0) + rr * 36 + q4 * 4;
        CP16(sb + (dof << 2), (mat ? qL : qH) + gb);
    }
    CP_COMMIT();

#define A_ISSUE(ch) do {                                                         \
        const uint32_t _sbase = 9216u + ((uint32_t)((ch) & 1)) * 4864u;          \
        _Pragma("unroll")                                                        \
        for (int k = 0; k < 4; k++) {                                            \
            const int i = tid + k * 256;                                         \
            if (i < 512) {                                                       \
                const int mat = i >> 8, rr = (i & 255) >> 3, q4 = i & 7;         \
                const size_t gb = (((size_t)(b * KANCH + (ch) * 32 + rr) * 128   \
                                    + h * 8 + q4)) << 4;                         \
                const uint32_t dof = _sbase + (mat ? 1152u : 0u) + rr * 36 + q4 * 4; \
                CP16(sb + (dof << 2), (mat ? kL : kH) + gb);                     \
            } else {                                                             \
                const int j = i - 512;                                           \
                const int mat = j >> 8, dd = (j & 255) >> 2, q4 = j & 3;         \
                const size_t gb = (((size_t)((b * NHEAD + h) * HDIM + dd) * 32   \
                                    + (ch) * 4 + q4)) << 4;                      \
                const uint32_t dof = _sbase + 2304u + (mat ? 1280u : 0u) + dd * 20 + q4 * 4; \
                CP16(sb + (dof << 2), (mat ? vL : vH) + gb);                     \
            }                                                                    \
        }                                                                        \
        CP_COMMIT();                                                             \
    } while (0)

    A_ISSUE(0);
    asm volatile("cp.async.wait_group 0;");
    __syncthreads();

    // Persistent Q fragments
    uint32_t qh[4][4], ql[4][4];
#pragma unroll
    for (int ks = 0; ks < 4; ks++) {
        const int rA0 = (wr + g) * 36 + ks * 8 + t;
        const int rA1 = (wr + 8 + g) * 36 + ks * 8 + t;
        qh[ks][0] = sma[rA0]; qh[ks][1] = sma[rA1];
        qh[ks][2] = sma[rA0 + 4]; qh[ks][3] = sma[rA1 + 4];
        ql[ks][0] = sma[4608 + rA0]; ql[ks][1] = sma[4608 + rA1];
        ql[ks][2] = sma[4608 + rA0 + 4]; ql[ks][3] = sma[4608 + rA1 + 4];
    }

    float o[8][4];
#pragma unroll
    for (int i = 0; i < 8; i++)
#pragma unroll
        for (int j = 0; j < 4; j++) o[i][j] = 0.f;
    float lA = 0.f, lB = 0.f;

    for (int ch = 0; ch < 8; ch++) {
        if (ch + 1 < 8) A_ISSUE(ch + 1);

        const uint32_t* st = sma + 9216 + (ch & 1) * 4864;
        const uint32_t* ksh = st;
        const uint32_t* ksl = st + 1152;
        const uint32_t* vsh = st + 2304;
        const uint32_t* vsl = st + 3584;

        // ---- Scores for this 32-key chunk (fp16 3-product) ----
        float s[4][4];
#pragma unroll
        for (int i = 0; i < 4; i++)
#pragma unroll
            for (int j = 0; j < 4; j++) s[i][j] = 0.f;
#pragma unroll
        for (int nfl = 0; nfl < 4; nfl++) {
#pragma unroll
            for (int ks = 0; ks < 4; ks++) {
                const int rb = (nfl * 8 + g) * 36 + ks * 8 + t;
                const uint32_t b0h = ksh[rb], b1h = ksh[rb + 4];
                const uint32_t b0l = ksl[rb], b1l = ksl[rb + 4];
                mma_f16(s[nfl], qh[ks], b0h, b1h);
                mma_f16(s[nfl], qh[ks], b0l, b1l);
                mma_f16(s[nfl], ql[ks], b0h, b1h);
            }
        }

        // ---- Fixed-shift softmax: p = exp(s*SCALE) directly ----
#pragma unroll
        for (int nf = 0; nf < 4; nf++) {
            s[nf][0] = __expf(s[nf][0] * SCALE); lA += s[nf][0];
            s[nf][1] = __expf(s[nf][1] * SCALE); lA += s[nf][1];
            s[nf][2] = __expf(s[nf][2] * SCALE); lB += s[nf][2];
            s[nf][3] = __expf(s[nf][3] * SCALE); lB += s[nf][3];
        }

        // ---- P·V for this chunk (fp16 3-product) ----
#pragma unroll
        for (int kk = 0; kk < 2; kk++) {
            const int j0 = kk * 2;
            uint32_t ah[4], al[4];
            split2h(s[j0][0],     s[j0][1],     ah[0], al[0]);
            split2h(s[j0][2],     s[j0][3],     ah[1], al[1]);
            split2h(s[j0 + 1][0], s[j0 + 1][1], ah[2], al[2]);
            split2h(s[j0 + 1][2], s[j0 + 1][3], ah[3], al[3]);
#pragma unroll
            for (int nf = 0; nf < 8; nf++) {
                const int rb = (nf * 8 + g) * 20 + kk * 8 + t;
                const uint32_t b0h = vsh[rb], b1h = vsh[rb + 4];
                const uint32_t b0l = vsl[rb], b1l = vsl[rb + 4];
                mma_f16(o[nf], ah, b0h, b1h);
                mma_f16(o[nf], ah, b0l, b1l);
                mma_f16(o[nf], al, b0h, b1h);
            }
        }

        if (ch + 1 < 8) {
            asm volatile("cp.async.wait_group 0;");
            __syncthreads();
        }
    }
#undef A_ISSUE

    // ---- Final l reduction across the quad, normalize, store ctx ----
    lA += __shfl_xor_sync(0xffffffffu, lA, 1);
    lA += __shfl_xor_sync(0xffffffffu, lA, 2);
    lB += __shfl_xor_sync(0xffffffffu, lB, 1);
    lB += __shfl_xor_sync(0xffffffffu, lB, 2);
    const float invA = 1.f / lA, invB = 1.f / lB;

    const size_t rowA = (size_t)(b * NTOK + n0 + wr + g);
    const size_t rowB = rowA + 8;
    uint32_t* Hi = (uint32_t*)g_chi;
    uint32_t* Lo = (uint32_t*)g_clo;
#pragma unroll
    for (int nf = 0; nf < 8; nf++) {
        const int col = h * 64 + nf * 8 + t * 2;
        uint32_t h0, l0, h1, l1;
        split2h(o[nf][0] * invA, o[nf][1] * invA, h0, l0);
        split2h(o[nf][2] * invB, o[nf][3] * invB, h1, l1);
        Hi[rowA * 512 + col / 2] = h0;
        Lo[rowA * 512 + col / 2] = l0;
        Hi[rowB * 512 + col / 2] = h1;
        Lo[rowB * 512 + col / 2] = l1;
    }
}

// ---------------------------------------------------------------------------
// kernel_launch
// ---------------------------------------------------------------------------
extern "C" void kernel_launch(void* const* d_in, const int* in_sizes, int n_in,
                              void* d_out, int out_size)
{
    const float* x   = (const float*)d_in[0];
    const float* Wq  = (const float*)d_in[1];
    const float* bq  = (const float*)d_in[2];
    const float* Wk  = (const float*)d_in[3];
    const float* bk  = (const float*)d_in[4];
    const float* Wv  = (const float*)d_in[5];
    const float* bv  = (const float*)d_in[6];
    const float* Wqt = (const float*)d_in[7];
    const float* bqt = (const float*)d_in[8];
    const float* Wo  = (const float*)d_in[9];
    const float* bo  = (const float*)d_in[10];
    float* out = (float*)d_out;

    static bool attr_done = false;
    if (!attr_done) {
        cudaFuncSetAttribute(proj_kernel,     cudaFuncAttributeMaxDynamicSharedMemorySize, GEMM_SMEM);
        cudaFuncSetAttribute(oproj_kernel,    cudaFuncAttributeMaxDynamicSharedMemorySize, GEMM_SMEM);
        cudaFuncSetAttribute(attn_mma_kernel, cudaFuncAttributeMaxDynamicSharedMemorySize, ATTN_SMEM);
        attr_done = true;
    }

    // Fused prep: x split (4096 blocks) + weight transpose/round (5120 blocks)
    prep_kernel<<<9216, 256>>>(x, Wq, Wqt, Wk, Wv, Wo);

    proj_kernel<<<1152, 256, GEMM_SMEM>>>(bq, bqt, bk, bv);

    attn_mma_kernel<<<dim3(NTOK / 128, NHEAD, BATCH), 256, ATTN_SMEM>>>();

    oproj_kernel<<<dim3(8, 128), 256, GEMM_SMEM>>>(bo, out);
}

// round 17
// speedup vs baseline: 1.6260x; 1.2628x over previous
#include <cuda_runtime.h>
#include <cuda_fp16.h>
#include <math.h>
#include <stdint.h>

// Problem constants
#define BATCH   4
#define NTOK    4096
#define DMODEL  1024
#define NHEAD   16
#define HDIM    64
#define KANCH   256
#define MROWS   (BATCH * NTOK)        // 16384
#define SCALE   0.125f

// ---------------------------------------------------------------------------
// Scratch (device globals). RULE: device symbols referenced ONLY from device
// code. Precision plan: x and Q keep exact fp16 hi/lo splits; K, V, ctx and
// all weights are rounded ONCE to fp16 (each ~2.4e-4 rel err, budgeted).
// ---------------------------------------------------------------------------
__device__ __align__(16) __half g_xhi[MROWS * DMODEL];
__device__ __align__(16) __half g_xlo[MROWS * DMODEL];
__device__ __align__(16) __half g_Qhi[MROWS * DMODEL];
__device__ __align__(16) __half g_Qlo[MROWS * DMODEL];
__device__ __align__(16) __half g_K[BATCH * KANCH * DMODEL];          // single
__device__ __align__(16) __half g_Vt[BATCH * NHEAD * HDIM * KANCH];   // single, [b][h][d][key]
__device__ __align__(16) __half g_ctx[MROWS * DMODEL];                // single
__device__ __align__(16) __half g_W[5][DMODEL * DMODEL];  // 0=Wq 1=Wqt 2=Wk 3=Wv 4=Wo

// ---------------------------------------------------------------------------
// Primitives
// ---------------------------------------------------------------------------
__device__ __forceinline__ uint32_t smem_to_u32(const void* p) {
    uint32_t a;
    asm("{ .reg .u64 t; cvta.to.shared.u64 t, %1; cvt.u32.u64 %0, t; }" : "=r"(a) : "l"(p));
    return a;
}
#define CP16(d, s) \
    asm volatile("cp.async.cg.shared.global [%0], [%1], 16;" :: "r"(d), "l"(s))
#define CP_COMMIT() asm volatile("cp.async.commit_group;")

__device__ __forceinline__ void mma_f16(float* c, const uint32_t* a,
                                        uint32_t b0, uint32_t b1) {
    asm volatile(
        "mma.sync.aligned.m16n8k16.row.col.f32.f16.f16.f32 "
        "{%0,%1,%2,%3}, {%4,%5,%6,%7}, {%8,%9}, {%0,%1,%2,%3};"
        : "+f"(c[0]), "+f"(c[1]), "+f"(c[2]), "+f"(c[3])
        : "r"(a[0]), "r"(a[1]), "r"(a[2]), "r"(a[3]), "r"(b0), "r"(b1));
}

__device__ __forceinline__ void split2h(float v0, float v1, uint32_t& hi, uint32_t& lo) {
    __half h0 = __float2half_rn(v0), h1 = __float2half_rn(v1);
    __half2 hh = __halves2half2(h0, h1);
    __half2 ll = __halves2half2(__float2half_rn(v0 - __half2float(h0)),
                                __float2half_rn(v1 - __half2float(h1)));
    hi = *reinterpret_cast<uint32_t*>(&hh);
    lo = *reinterpret_cast<uint32_t*>(&ll);
}
__device__ __forceinline__ uint32_t pack2h(float v0, float v1) {
    __half2 hh = __halves2half2(__float2half_rn(v0), __float2half_rn(v1));
    return *reinterpret_cast<uint32_t*>(&hh);
}

// 16B-chunk XOR swizzle on 64B rows (16 u32, chunks c∈0..3)
#define SW64(row, cc) ((((row) << 4)) + ((((cc) ^ (((row) >> 1) & 3))) << 2))

// ---------------------------------------------------------------------------
// 2-product GEMM: acc = (Ah+Al) @ W^T. 3 mats/stage, 48 KB smem, 2 CTAs/SM.
// ---------------------------------------------------------------------------
#define GEMM_SMEM 49152

__device__ __forceinline__ void gemm_main2(
    const __half* __restrict__ Ahi, const __half* __restrict__ Alo,
    const __half* __restrict__ W, float acc[2][8][4])
{
    extern __shared__ uint32_t sm[];
    const int tid  = threadIdx.x;
    const int lane = tid & 31;
    const int wid  = tid >> 5;
    const int wm   = wid >> 1;
    const int wn   = wid & 1;
    const int g    = lane >> 2;
    const int t    = lane & 3;

#pragma unroll
    for (int i = 0; i < 2; i++)
#pragma unroll
        for (int j = 0; j < 8; j++)
#pragma unroll
            for (int k = 0; k < 4; k++) acc[i][j][k] = 0.f;

    const char* gp[3] = { (const char*)Ahi, (const char*)Alo, (const char*)W };

    const int row = tid >> 1;
    const int c0  = (tid & 1) * 2;
    const uint32_t swo0 = SW64(row, c0);
    const uint32_t swo1 = SW64(row, c0 + 1);
    const uint32_t sb   = smem_to_u32(sm);
    const size_t   gof  = (size_t)row * 512 + c0 * 4;

#define G_ISSUE(c) do {                                                        \
        const uint32_t _st = ((uint32_t)((c) & 1)) * 6144u;                    \
        const size_t _gb = (gof + (size_t)(c) * 16) << 2;                      \
        _Pragma("unroll")                                                      \
        for (int m = 0; m < 3; m++) {                                          \
            CP16(sb + ((_st + m * 2048u + swo0) << 2), gp[m] + _gb);           \
            CP16(sb + ((_st + m * 2048u + swo1) << 2), gp[m] + _gb + 16);      \
        }                                                                      \
        CP_COMMIT();                                                           \
    } while (0)

    G_ISSUE(0);

    for (int c = 0; c < 32; c++) {
        asm volatile("cp.async.wait_group 0;");
        __syncthreads();
        if (c + 1 < 32) G_ISSUE(c + 1);

        const uint32_t* st = sm + (c & 1) * 6144;
#pragma unroll
        for (int ks = 0; ks < 2; ks++) {
            const int cA = ks * 2;
            uint32_t aHi[2][4], aLo[2][4];
#pragma unroll
            for (int mf = 0; mf < 2; mf++) {
                const int rA0 = wm * 32 + mf * 16 + g;
                const int rA1 = rA0 + 8;
                aHi[mf][0] = st[SW64(rA0, cA) + t];
                aHi[mf][1] = st[SW64(rA1, cA) + t];
                aHi[mf][2] = st[SW64(rA0, cA + 1) + t];
                aHi[mf][3] = st[SW64(rA1, cA + 1) + t];
                aLo[mf][0] = st[2048 + SW64(rA0, cA) + t];
                aLo[mf][1] = st[2048 + SW64(rA1, cA) + t];
                aLo[mf][2] = st[2048 + SW64(rA0, cA + 1) + t];
                aLo[mf][3] = st[2048 + SW64(rA1, cA + 1) + t];
            }
#pragma unroll
            for (int nq = 0; nq < 4; nq++) {
#pragma unroll
                for (int hf = 0; hf < 2; hf++) {
                    const int rB = wn * 64 + nq * 16 + hf * 8 + g;
                    const uint32_t b0 = st[4096 + SW64(rB, cA) + t];
                    const uint32_t b1 = st[4096 + SW64(rB, cA + 1) + t];
                    float* cc0 = acc[0][nq * 2 + hf];
                    float* cc1 = acc[1][nq * 2 + hf];
                    mma_f16(cc0, aHi[0], b0, b1);
                    mma_f16(cc0, aLo[0], b0, b1);
                    mma_f16(cc1, aHi[1], b0, b1);
                    mma_f16(cc1, aLo[1], b0, b1);
                }
            }
        }
    }
#undef G_ISSUE
}

// ---------------------------------------------------------------------------
// 1-product GEMM: acc = A @ W^T (both single fp16). 2 mats/stage, 32 KB smem.
// ---------------------------------------------------------------------------
#define GEMM1_SMEM 32768

__device__ __forceinline__ void gemm_main1(
    const __half* __restrict__ A, const __half* __restrict__ W,
    float acc[2][8][4])
{
    extern __shared__ uint32_t sm[];
    const int tid  = threadIdx.x;
    const int lane = tid & 31;
    const int wid  = tid >> 5;
    const int wm   = wid >> 1;
    const int wn   = wid & 1;
    const int g    = lane >> 2;
    const int t    = lane & 3;

#pragma unroll
    for (int i = 0; i < 2; i++)
#pragma unroll
        for (int j = 0; j < 8; j++)
#pragma unroll
            for (int k = 0; k < 4; k++) acc[i][j][k] = 0.f;

    const char* gp[2] = { (const char*)A, (const char*)W };

    const int row = tid >> 1;
    const int c0  = (tid & 1) * 2;
    const uint32_t swo0 = SW64(row, c0);
    const uint32_t swo1 = SW64(row, c0 + 1);
    const uint32_t sb   = smem_to_u32(sm);
    const size_t   gof  = (size_t)row * 512 + c0 * 4;

#define G_ISSUE(c) do {                                                        \
        const uint32_t _st = ((uint32_t)((c) & 1)) * 4096u;                    \
        const size_t _gb = (gof + (size_t)(c) * 16) << 2;                      \
        _Pragma("unroll")                                                      \
        for (int m = 0; m < 2; m++) {                                          \
            CP16(sb + ((_st + m * 2048u + swo0) << 2), gp[m] + _gb);           \
            CP16(sb + ((_st + m * 2048u + swo1) << 2), gp[m] + _gb + 16);      \
        }                                                                      \
        CP_COMMIT();                                                           \
    } while (0)

    G_ISSUE(0);

    for (int c = 0; c < 32; c++) {
        asm volatile("cp.async.wait_group 0;");
        __syncthreads();
        if (c + 1 < 32) G_ISSUE(c + 1);

        const uint32_t* st = sm + (c & 1) * 4096;
#pragma unroll
        for (int ks = 0; ks < 2; ks++) {
            const int cA = ks * 2;
            uint32_t aH[2][4];
#pragma unroll
            for (int mf = 0; mf < 2; mf++) {
                const int rA0 = wm * 32 + mf * 16 + g;
                const int rA1 = rA0 + 8;
                aH[mf][0] = st[SW64(rA0, cA) + t];
                aH[mf][1] = st[SW64(rA1, cA) + t];
                aH[mf][2] = st[SW64(rA0, cA + 1) + t];
                aH[mf][3] = st[SW64(rA1, cA + 1) + t];
            }
#pragma unroll
            for (int nq = 0; nq < 4; nq++) {
#pragma unroll
                for (int hf = 0; hf < 2; hf++) {
                    const int rB = wn * 64 + nq * 16 + hf * 8 + g;
                    const uint32_t b0 = st[2048 + SW64(rB, cA) + t];
                    const uint32_t b1 = st[2048 + SW64(rB, cA + 1) + t];
                    mma_f16(acc[0][nq * 2 + hf], aH[0], b0, b1);
                    mma_f16(acc[1][nq * 2 + hf], aH[1], b0, b1);
                }
            }
        }
    }
#undef G_ISSUE
}

// ---------------------------------------------------------------------------
// Fused projection kernel: 1152 linear tiles (Q: [0,1024), K: [1024,1088),
// V transposed: [1088,1152)). Q written hi/lo (exact); K, V rounded once.
// ---------------------------------------------------------------------------
__global__ void __launch_bounds__(256, 2) proj_kernel(
    const float* __restrict__ bq, const float* __restrict__ bqt,
    const float* __restrict__ bk, const float* __restrict__ bv)
{
    const int idx  = blockIdx.x;
    const int lane = threadIdx.x & 31, wid = threadIdx.x >> 5;
    const int wm = wid >> 1, wn = wid & 1, g = lane >> 2, t = lane & 3;
    float acc[2][8][4];

    if (idx < 1024) {
        const int Mb = (idx >> 3) * 128;
        const int Nb = (idx & 7) * 128;
        const bool anchor = (Mb % NTOK) < KANCH;
        const int w = anchor ? 0 : 1;
        gemm_main2(g_xhi + (size_t)Mb * DMODEL, g_xlo + (size_t)Mb * DMODEL,
                   g_W[w] + (size_t)Nb * DMODEL, acc);
        const float* bias = anchor ? bq : bqt;
        uint32_t* Hi = (uint32_t*)g_Qhi;
        uint32_t* Lo = (uint32_t*)g_Qlo;
#pragma unroll
        for (int mf = 0; mf < 2; mf++)
#pragma unroll
            for (int nf = 0; nf < 8; nf++) {
                const int row = Mb + wm * 32 + mf * 16 + g;
                const int col = Nb + wn * 64 + nf * 8 + t * 2;
                const float bx = bias[col], by = bias[col + 1];
                uint32_t h0, l0, h1, l1;
                split2h(acc[mf][nf][0] + bx, acc[mf][nf][1] + by, h0, l0);
                split2h(acc[mf][nf][2] + bx, acc[mf][nf][3] + by, h1, l1);
                Hi[(size_t)row * 512 + col / 2] = h0;
                Lo[(size_t)row * 512 + col / 2] = l0;
                Hi[(size_t)(row + 8) * 512 + col / 2] = h1;
                Lo[(size_t)(row + 8) * 512 + col / 2] = l1;
            }
    } else if (idx < 1088) {
        const int rem = idx - 1024;
        const int Mt = rem >> 3;
        const int Nb = (rem & 7) * 128;
        const int arow = (Mt >> 1) * NTOK + (Mt & 1) * 128;
        gemm_main2(g_xhi + (size_t)arow * DMODEL, g_xlo + (size_t)arow * DMODEL,
                   g_W[2] + (size_t)Nb * DMODEL, acc);
        uint32_t* Kd = (uint32_t*)g_K;
#pragma unroll
        for (int mf = 0; mf < 2; mf++)
#pragma unroll
            for (int nf = 0; nf < 8; nf++) {
                const int row = Mt * 128 + wm * 32 + mf * 16 + g;
                const int col = Nb + wn * 64 + nf * 8 + t * 2;
                const float bx = bk[col], by = bk[col + 1];
                Kd[(size_t)row * 512 + col / 2] =
                    pack2h(acc[mf][nf][0] + bx, acc[mf][nf][1] + by);
                Kd[(size_t)(row + 8) * 512 + col / 2] =
                    pack2h(acc[mf][nf][2] + bx, acc[mf][nf][3] + by);
            }
    } else {
        const int rem = idx - 1088;
        const int Mt = rem >> 3;
        const int Nb = (rem & 7) * 128;
        const int arow = (Mt >> 1) * NTOK + (Mt & 1) * 128;
        gemm_main2(g_xhi + (size_t)arow * DMODEL, g_xlo + (size_t)arow * DMODEL,
                   g_W[3] + (size_t)Nb * DMODEL, acc);
#pragma unroll
        for (int mf = 0; mf < 2; mf++)
#pragma unroll
            for (int nf = 0; nf < 8; nf++) {
                const int col = Nb + wn * 64 + nf * 8 + t * 2;
                const int h = col >> 6, d = col & 63;
#pragma unroll
                for (int rr = 0; rr < 2; rr++) {
                    const int a = Mt * 128 + wm * 32 + mf * 16 + g + rr * 8;
                    const int b = a >> 8, tok = a & 255;
                    const size_t i0 = ((size_t)((b * NHEAD + h) * HDIM + d)) * KANCH + tok;
                    g_Vt[i0] = __float2half_rn(acc[mf][nf][rr * 2 + 0] + bv[col]);
                    g_Vt[i0 + KANCH] = __float2half_rn(acc[mf][nf][rr * 2 + 1] + bv[col + 1]);
                }
            }
    }
}

// ---- Output projection (1-product): ctx @ Wo + bo -> fp32 out ----
__global__ void __launch_bounds__(256, 2) oproj_kernel(
    const float* __restrict__ bo, float* __restrict__ out)
{
    const int Mb = blockIdx.y * 128;
    const int Nb = blockIdx.x * 128;
    float acc[2][8][4];
    gemm_main1(g_ctx + (size_t)Mb * DMODEL, g_W[4] + (size_t)Nb * DMODEL, acc);
    const int lane = threadIdx.x & 31, wid = threadIdx.x >> 5;
    const int wm = wid >> 1, wn = wid & 1, g = lane >> 2, t = lane & 3;
#pragma unroll
    for (int mf = 0; mf < 2; mf++)
#pragma unroll
        for (int nf = 0; nf < 8; nf++) {
            const int row = Mb + wm * 32 + mf * 16 + g;
            const int col = Nb + wn * 64 + nf * 8 + t * 2;
            const float bx = bo[col], by = bo[col + 1];
            float2 v0 = { acc[mf][nf][0] + bx, acc[mf][nf][1] + by };
            float2 v1 = { acc[mf][nf][2] + bx, acc[mf][nf][3] + by };
            *reinterpret_cast<float2*>(out + (size_t)row * DMODEL + col) = v0;
            *reinterpret_cast<float2*>(out + (size_t)(row + 8) * DMODEL + col) = v1;
        }
}

// ---------------------------------------------------------------------------
// Fused prep: blocks [0,4096) split x (fp16 hi/lo); blocks [4096,9216)
// transpose weights, rounding once to fp16.
// ---------------------------------------------------------------------------
__global__ void __launch_bounds__(256) prep_kernel(
    const float* __restrict__ x,
    const float* __restrict__ Wq, const float* __restrict__ Wqt,
    const float* __restrict__ Wk, const float* __restrict__ Wv,
    const float* __restrict__ Wo)
{
    __shared__ float tbuf[32][33];
    const int tid = threadIdx.x;

    if (blockIdx.x < 4096) {
        const int n4 = MROWS * DMODEL / 4;
        for (int i = blockIdx.x * 256 + tid; i < n4; i += 4096 * 256) {
            float4 v = reinterpret_cast<const float4*>(x)[i];
            uint32_t hA, lA, hB, lB;
            split2h(v.x, v.y, hA, lA);
            split2h(v.z, v.w, hB, lB);
            reinterpret_cast<uint32_t*>(g_xhi)[i * 2 + 0] = hA;
            reinterpret_cast<uint32_t*>(g_xhi)[i * 2 + 1] = hB;
            reinterpret_cast<uint32_t*>(g_xlo)[i * 2 + 0] = lA;
            reinterpret_cast<uint32_t*>(g_xlo)[i * 2 + 1] = lB;
        }
        return;
    }

    const int widx = blockIdx.x - 4096;
    const int z   = widx >> 10;
    const int rem = widx & 1023;
    const int bx  = rem & 31;
    const int by  = rem >> 5;
    const int tx  = tid & 31;
    const int ty  = tid >> 5;

    const float* src;
    switch (z) {
        case 0: src = Wq;  break;
        case 1: src = Wqt; break;
        case 2: src = Wk;  break;
        case 3: src = Wv;  break;
        default: src = Wo; break;
    }
    __half* dh = g_W[z];
    const int n0 = bx * 32, k0 = by * 32;
    for (int i = ty; i < 32; i += 8)
        tbuf[i][tx] = src[(size_t)(k0 + i) * DMODEL + n0 + tx];
    __syncthreads();
    for (int i = ty; i < 32; i += 8)
        dh[(size_t)(n0 + i) * DMODEL + k0 + tx] = __float2half_rn(tbuf[tx][i]);
}

// ---------------------------------------------------------------------------
// Flash tensor-core attention: 2-product QK (Qhi/Qlo x K) and PV (Phi/Plo x V),
// K and V single fp16. Fixed-shift softmax. 2-stage cp.async K/V pipeline.
// smem u32: Q hi at 0 (4608), Q lo at 4608, stage s at 9216 + s*2432:
//   K +0 (1152), V +1152 (1280).  Total = (9216 + 2*2432)*4 = 56320 B.
// ---------------------------------------------------------------------------
#define ATTN_SMEM 56320

__global__ void __launch_bounds__(256, 2) attn_mma_kernel()
{
    extern __shared__ uint32_t sma[];
    const uint32_t sb = smem_to_u32(sma);

    const int b = blockIdx.z, h = blockIdx.y;
    const int n0 = blockIdx.x * 128;
    const int tid = threadIdx.x, lane = tid & 31, wid = tid >> 5;
    const int g = lane >> 2, t = lane & 3;
    const int wr = wid * 16;

    const char* qH = (const char*)g_Qhi;
    const char* qL = (const char*)g_Qlo;
    const char* kP = (const char*)g_K;
    const char* vP = (const char*)g_Vt;

    // ---- Q tile via cp.async: 2048 x 16B ----
#pragma unroll
    for (int k = 0; k < 8; k++) {
        const int i = tid + k * 256;
        const int mat = i >> 10, rr = (i & 1023) >> 3, q4 = i & 7;
        const size_t gb = (((size_t)(b * NTOK + n0 + rr) * 128 + h * 8 + q4)) << 4;
        const uint32_t dof = (uint32_t)(mat ? 4608 : 0) + rr * 36 + q4 * 4;
        CP16(sb + (dof << 2), (mat ? qL : qH) + gb);
    }
    CP_COMMIT();

#define A_ISSUE(ch) do {                                                         \
        const uint32_t _sbase = 9216u + ((uint32_t)((ch) & 1)) * 2432u;          \
        _Pragma("unroll")                                                        \
        for (int k = 0; k < 2; k++) {                                            \
            const int i = tid + k * 256;                                         \
            if (i < 256) {                                                       \
                const int rr = i >> 3, q4 = i & 7;                               \
                const size_t gb = (((size_t)(b * KANCH + (ch) * 32 + rr) * 128   \
                                    + h * 8 + q4)) << 4;                         \
                const uint32_t dof = _sbase + rr * 36 + q4 * 4;                  \
                CP16(sb + (dof << 2), kP + gb);                                  \
            } else {                                                             \
                const int j = i - 256;                                           \
                const int dd = j >> 2, q4 = j & 3;                               \
                const size_t gb = (((size_t)((b * NHEAD + h) * HDIM + dd) * 32   \
                                    + (ch) * 4 + q4)) << 4;                      \
                const uint32_t dof = _sbase + 1152u + dd * 20 + q4 * 4;          \
                CP16(sb + (dof << 2), vP + gb);                                  \
            }                                                                    \
        }                                                                        \
        CP_COMMIT();                                                             \
    } while (0)

    A_ISSUE(0);
    asm volatile("cp.async.wait_group 0;");
    __syncthreads();

    // Persistent Q fragments
    uint32_t qh[4][4], ql[4][4];
#pragma unroll
    for (int ks = 0; ks < 4; ks++) {
        const int rA0 = (wr + g) * 36 + ks * 8 + t;
        const int rA1 = (wr + 8 + g) * 36 + ks * 8 + t;
        qh[ks][0] = sma[rA0]; qh[ks][1] = sma[rA1];
        qh[ks][2] = sma[rA0 + 4]; qh[ks][3] = sma[rA1 + 4];
        ql[ks][0] = sma[4608 + rA0]; ql[ks][1] = sma[4608 + rA1];
        ql[ks][2] = sma[4608 + rA0 + 4]; ql[ks][3] = sma[4608 + rA1 + 4];
    }

    float o[8][4];
#pragma unroll
    for (int i = 0; i < 8; i++)
#pragma unroll
        for (int j = 0; j < 4; j++) o[i][j] = 0.f;
    float lA = 0.f, lB = 0.f;

    for (int ch = 0; ch < 8; ch++) {
        if (ch + 1 < 8) A_ISSUE(ch + 1);

        const uint32_t* st  = sma + 9216 + (ch & 1) * 2432;
        const uint32_t* ksh = st;
        const uint32_t* vsh = st + 1152;

        // ---- Scores (2-product: Qh*K + Ql*K) ----
        float s[4][4];
#pragma unroll
        for (int i = 0; i < 4; i++)
#pragma unroll
            for (int j = 0; j < 4; j++) s[i][j] = 0.f;
#pragma unroll
        for (int nfl = 0; nfl < 4; nfl++) {
#pragma unroll
            for (int ks = 0; ks < 4; ks++) {
                const int rb = (nfl * 8 + g) * 36 + ks * 8 + t;
                const uint32_t b0 = ksh[rb], b1 = ksh[rb + 4];
                mma_f16(s[nfl], qh[ks], b0, b1);
                mma_f16(s[nfl], ql[ks], b0, b1);
            }
        }

        // ---- Fixed-shift softmax ----
#pragma unroll
        for (int nf = 0; nf < 4; nf++) {
            s[nf][0] = __expf(s[nf][0] * SCALE); lA += s[nf][0];
            s[nf][1] = __expf(s[nf][1] * SCALE); lA += s[nf][1];
            s[nf][2] = __expf(s[nf][2] * SCALE); lB += s[nf][2];
            s[nf][3] = __expf(s[nf][3] * SCALE); lB += s[nf][3];
        }

        // ---- P·V (2-product: Ph*V + Pl*V) ----
#pragma unroll
        for (int kk = 0; kk < 2; kk++) {
            const int j0 = kk * 2;
            uint32_t ah[4], al[4];
            split2h(s[j0][0],     s[j0][1],     ah[0], al[0]);
            split2h(s[j0][2],     s[j0][3],     ah[1], al[1]);
            split2h(s[j0 + 1][0], s[j0 + 1][1], ah[2], al[2]);
            split2h(s[j0 + 1][2], s[j0 + 1][3], ah[3], al[3]);
#pragma unroll
            for (int nf = 0; nf < 8; nf++) {
                const int rb = (nf * 8 + g) * 20 + kk * 8 + t;
                const uint32_t b0 = vsh[rb], b1 = vsh[rb + 4];
                mma_f16(o[nf], ah, b0, b1);
                mma_f16(o[nf], al, b0, b1);
            }
        }

        if (ch + 1 < 8) {
            asm volatile("cp.async.wait_group 0;");
            __syncthreads();
        }
    }
#undef A_ISSUE

    // ---- Final l reduction, normalize, store ctx (single fp16) ----
    lA += __shfl_xor_sync(0xffffffffu, lA, 1);
    lA += __shfl_xor_sync(0xffffffffu, lA, 2);
    lB += __shfl_xor_sync(0xffffffffu, lB, 1);
    lB += __shfl_xor_sync(0xffffffffu, lB, 2);
    const float invA = 1.f / lA, invB = 1.f / lB;

    const size_t rowA = (size_t)(b * NTOK + n0 + wr + g);
    const size_t rowB = rowA + 8;
    uint32_t* Cd = (uint32_t*)g_ctx;
#pragma unroll
    for (int nf = 0; nf < 8; nf++) {
        const int col = h * 64 + nf * 8 + t * 2;
        Cd[rowA * 512 + col / 2] = pack2h(o[nf][0] * invA, o[nf][1] * invA);
        Cd[rowB * 512 + col / 2] = pack2h(o[nf][2] * invB, o[nf][3] * invB);
    }
}

// ---------------------------------------------------------------------------
// kernel_launch
// ---------------------------------------------------------------------------
extern "C" void kernel_launch(void* const* d_in, const int* in_sizes, int n_in,
                              void* d_out, int out_size)
{
    const float* x   = (const float*)d_in[0];
    const float* Wq  = (const float*)d_in[1];
    const float* bq  = (const float*)d_in[2];
    const float* Wk  = (const float*)d_in[3];
    const float* bk  = (const float*)d_in[4];
    const float* Wv  = (const float*)d_in[5];
    const float* bv  = (const float*)d_in[6];
    const float* Wqt = (const float*)d_in[7];
    const float* bqt = (const float*)d_in[8];
    const float* Wo  = (const float*)d_in[9];
    const float* bo  = (const float*)d_in[10];
    float* out = (float*)d_out;

    static bool attr_done = false;
    if (!attr_done) {
        cudaFuncSetAttribute(proj_kernel,     cudaFuncAttributeMaxDynamicSharedMemorySize, GEMM_SMEM);
        cudaFuncSetAttribute(attn_mma_kernel, cudaFuncAttributeMaxDynamicSharedMemorySize, ATTN_SMEM);
        attr_done = true;
    }

    // Fused prep: x split (4096 blocks) + weight transpose/round (5120 blocks)
    prep_kernel<<<9216, 256>>>(x, Wq, Wqt, Wk, Wv, Wo);

    proj_kernel<<<1152, 256, GEMM_SMEM>>>(bq, bqt, bk, bv);

    attn_mma_kernel<<<dim3(NTOK / 128, NHEAD, BATCH), 256, ATTN_SMEM>>>();

    oproj_kernel<<<dim3(8, 128), 256, GEMM1_SMEM>>>(bo, out);
}